// round 15
// baseline (speedup 1.0000x reference)
#include <cuda_runtime.h>
#include <cuda_fp16.h>
#include <math.h>
#include <cstdint>

#define BT    4096
#define TSEQ  2048
#define DM    2048
#define DQK   192
#define DV    128
#define NCAT  3712
#define ATT_SCALE 0.07216878364870323f
#define SCALE_L2  0.10412736773510762f                  // ATT_SCALE * log2(e)
#define SOFT_C    8.0f
#define NEG_BIG  -1e30f

// ---------------- scratch ----------------
__device__ __half g_x    [BT * DM];
__device__ __half g_wcat [NCAT * DM];
__device__ __half g_wukv_h[4096 * 512];
__device__ __half g_wo_h [DM * DM];
__device__ __half g_qroth[BT * 1024];
__device__ __half g_kroth[BT * 64];
__device__ __half g_dkv  [BT * 512];
__device__ __half g_attn [BT * DM];
__device__ __half g_qh [32 * TSEQ * DQK];
__device__ __half g_kh [32 * TSEQ * 128];
__device__ __half g_krh[ 2 * TSEQ * 64];
__device__ __half g_vh [32 * TSEQ * 128];

// ---------------- PTX helpers ----------------
__device__ __forceinline__ void cp16(uint32_t s, const void* g) {
    asm volatile("cp.async.cg.shared.global [%0], [%1], 16;" :: "r"(s), "l"(g) : "memory");
}
__device__ __forceinline__ uint32_t smem_u32(const void* p) {
    uint32_t a;
    asm("{ .reg .u64 t; cvta.to.shared.u64 t, %1; cvt.u32.u64 %0, t; }" : "=r"(a) : "l"(p));
    return a;
}
__device__ __forceinline__ void ldm4(uint32_t* r, uint32_t addr) {
    asm volatile("ldmatrix.sync.aligned.m8n8.x4.shared.b16 {%0,%1,%2,%3}, [%4];"
        : "=r"(r[0]), "=r"(r[1]), "=r"(r[2]), "=r"(r[3]) : "r"(addr));
}
__device__ __forceinline__ void ldm4t(uint32_t* r, uint32_t addr) {
    asm volatile("ldmatrix.sync.aligned.m8n8.x4.trans.shared.b16 {%0,%1,%2,%3}, [%4];"
        : "=r"(r[0]), "=r"(r[1]), "=r"(r[2]), "=r"(r[3]) : "r"(addr));
}
__device__ __forceinline__ void mma16816(float* c, const uint32_t* a, const uint32_t* b) {
    asm volatile(
        "mma.sync.aligned.m16n8k16.row.col.f32.f16.f16.f32 "
        "{%0,%1,%2,%3}, {%4,%5,%6,%7}, {%8,%9}, {%0,%1,%2,%3};"
        : "+f"(c[0]), "+f"(c[1]), "+f"(c[2]), "+f"(c[3])
        : "r"(a[0]), "r"(a[1]), "r"(a[2]), "r"(a[3]), "r"(b[0]), "r"(b[1]));
}
__device__ __forceinline__ void mma16816b(float* c, const uint32_t* a, uint32_t b0, uint32_t b1) {
    asm volatile(
        "mma.sync.aligned.m16n8k16.row.col.f32.f16.f16.f32 "
        "{%0,%1,%2,%3}, {%4,%5,%6,%7}, {%8,%9}, {%0,%1,%2,%3};"
        : "+f"(c[0]), "+f"(c[1]), "+f"(c[2]), "+f"(c[3])
        : "r"(a[0]), "r"(a[1]), "r"(a[2]), "r"(a[3]), "r"(b0), "r"(b1));
}
__device__ __forceinline__ float ex2(float x) {
    float y;
    asm("ex2.approx.f32 %0, %1;" : "=f"(y) : "f"(x));
    return y;
}

// ---------------- fused converts ----------------
#define N4_X    2097152
#define N4_CAT  1867776
#define N4_UKV  524288
#define N4_WO   1048576
#define N4_ALL  (N4_X + N4_CAT + N4_UKV + N4_WO)

__global__ void conv_all(const float* __restrict__ x,
                         const float* __restrict__ wq, const float* __restrict__ wqr,
                         const float* __restrict__ wdkv, const float* __restrict__ wkr,
                         const float* __restrict__ wukv, const float* __restrict__ wo,
                         __half* __restrict__ gx, __half* __restrict__ gwcat,
                         __half* __restrict__ gwukv, __half* __restrict__ gwo) {
    int i = blockIdx.x * blockDim.x + threadIdx.x;
    if (i >= N4_ALL) return;
    const float* src;
    __half* dst;
    int si, di;
    float sc = 1.f;
    if (i < N4_X) {
        src = x; dst = gx; si = di = i;
    } else if (i < N4_X + N4_CAT) {
        di = i - N4_X;
        dst = gwcat;
        const int row = (int)(((size_t)di * 4) >> 11);
        if (row < 2048)      { src = wq;   si = di;              sc = SCALE_L2; }
        else if (row < 3072) { src = wqr;  si = di - 2048 * 512; sc = SCALE_L2; }
        else if (row < 3584) { src = wdkv; si = di - 3072 * 512; }
        else                 { src = wkr;  si = di - 3584 * 512; }
    } else if (i < N4_X + N4_CAT + N4_UKV) {
        src = wukv; dst = gwukv; si = di = i - N4_X - N4_CAT;
    } else {
        src = wo; dst = gwo; si = di = i - N4_X - N4_CAT - N4_UKV;
    }
    float4 v = ((const float4*)src)[si];
    ((__half2*)dst)[di*2]   = __halves2half2(__float2half_rn(v.x * sc), __float2half_rn(v.y * sc));
    ((__half2*)dst)[di*2+1] = __halves2half2(__float2half_rn(v.z * sc), __float2half_rn(v.w * sc));
}

// ---------------- rope helper ----------------
__device__ __forceinline__ void rope_pair(float x1, float x2, int i, int t,
                                          float& o1, float& o2) {
    const float invf = (float)exp2(-(double)i * (13.287712379549449 / 32.0));
    const float angf = (float)t * invf;
    double sd, cd;
    sincos((double)angf, &sd, &cd);
    const float s = (float)sd, c = (float)cd;
    o1 = x1 * c - x2 * s;
    o2 = x2 * c + x1 * s;
}
#define NROPE_Q (32 * TSEQ * 32)
#define NROPE_K (2 * TSEQ * 32)

// ---------------- single-pass fp16 NT GEMM ----------------
template<int BN, int EPI>
__global__ __launch_bounds__(256, 2)
void gemm_s(const __half* __restrict__ A, const __half* __restrict__ B,
            float* __restrict__ C, __half* __restrict__ CH, __half* __restrict__ CH2,
            __half* __restrict__ CH3, __half* __restrict__ CH4,
            int M, int N, int K)
{
    constexpr int ATILE = 128 * 128;
    constexpr int BTILE = BN * 128;
    constexpr int STG   = ATILE + BTILE;
    constexpr int WN = 4;
    constexpr int MT = 4;
    constexpr int NT = 4;

    extern __shared__ __align__(128) char smem[];
    const uint32_t d0 = smem_u32(smem);

    const int tid = threadIdx.x;
    const int wid = tid >> 5, lane = tid & 31;
    const int wn = wid % WN, wm = wid / WN;
    const int m0 = blockIdx.y * 128;
    const int n0 = blockIdx.x * BN;
    const int l7 = lane & 7;

    float acc[MT][NT][4];
#pragma unroll
    for (int i = 0; i < MT; ++i)
#pragma unroll
        for (int j = 0; j < NT; ++j)
#pragma unroll
            for (int q = 0; q < 4; ++q) acc[i][j][q] = 0.f;

    uint32_t arow[MT], brow[NT / 2];
    const int a_r = lane & 15;
    const int a_kh = lane >> 4;
    const int b_n = ((lane >> 4) << 3) + (lane & 7);
    const int b_kh = (lane >> 3) & 1;
#pragma unroll
    for (int mt = 0; mt < MT; ++mt) arow[mt] = (uint32_t)((wm * 64 + mt * 16 + a_r) * 128);
#pragma unroll
    for (int np = 0; np < NT / 2; ++np) brow[np] = (uint32_t)((wn * 32 + np * 16 + b_n) * 128);

    const int T = K >> 6;
    auto load_tile = [&](int t) {
        if (t < T) {
            const uint32_t d = d0 + (uint32_t)(t % 3) * STG;
            const int k0 = t * 64;
#pragma unroll
            for (int j = 0; j < 4; ++j) {
                const int c = tid + j * 256;
                const int row = c >> 3, ch = c & 7;
                const uint32_t sw = (uint32_t)(row * 128 + ((ch ^ (row & 7)) << 4));
                cp16(d + sw, A + (size_t)(m0 + row) * K + k0 + ch * 8);
            }
#pragma unroll
            for (int j = 0; j < BN / 32; ++j) {
                const int c = tid + j * 256;
                const int row = c >> 3, ch = c & 7;
                const uint32_t sw = (uint32_t)(row * 128 + ((ch ^ (row & 7)) << 4));
                cp16(d + ATILE + sw, B + (size_t)(n0 + row) * K + k0 + ch * 8);
            }
        }
        asm volatile("cp.async.commit_group;" ::: "memory");
    };

    load_tile(0);
    load_tile(1);

    for (int t = 0; t < T; ++t) {
        asm volatile("cp.async.wait_group 1;" ::: "memory");
        __syncthreads();
        load_tile(t + 2);

        const uint32_t AS = d0 + (uint32_t)(t % 3) * STG;
        const uint32_t BS = AS + ATILE;

#pragma unroll
        for (int kk = 0; kk < 4; ++kk) {
            const uint32_t aoff = (uint32_t)(((kk * 2 + a_kh) ^ l7) << 4);
            const uint32_t boff = (uint32_t)(((kk * 2 + b_kh) ^ l7) << 4);
            uint32_t af[MT][4], bf[NT / 2][4];
#pragma unroll
            for (int mt = 0; mt < MT; ++mt)
                ldm4(af[mt], AS + arow[mt] + aoff);
#pragma unroll
            for (int np = 0; np < NT / 2; ++np)
                ldm4(bf[np], BS + brow[np] + boff);
#pragma unroll
            for (int mt = 0; mt < MT; ++mt)
#pragma unroll
                for (int nt = 0; nt < NT; ++nt)
                    mma16816(acc[mt][nt], af[mt], &bf[nt >> 1][(nt & 1) * 2]);
        }
    }

    const int cr = lane >> 2;
    const int cc = (lane & 3) * 2;
#pragma unroll
    for (int mt = 0; mt < MT; ++mt) {
        const int r0 = m0 + wm * 64 + mt * 16 + cr;
#pragma unroll
        for (int nt = 0; nt < NT; ++nt) {
            const int col = n0 + wn * 32 + nt * 8 + cc;
            if constexpr (EPI == 0) {
                *(float2*)(C + (size_t)r0 * N + col)       = make_float2(acc[mt][nt][0], acc[mt][nt][1]);
                *(float2*)(C + (size_t)(r0 + 8) * N + col) = make_float2(acc[mt][nt][2], acc[mt][nt][3]);
            } else {
#pragma unroll
                for (int hf = 0; hf < 2; ++hf) {
                    __half2 h2 = __float22half2_rn(
                        make_float2(acc[mt][nt][hf*2], acc[mt][nt][hf*2+1]));
                    const int r = r0 + hf * 8;
                    const int b = r >> 11, tt = r & 2047;
                    if constexpr (EPI == 3) {
                        const int h = col >> 8, c = col & 255;
                        const size_t base = ((size_t)((b * 16 + h) * 2048 + tt)) * 128;
                        if (c < 128) *(__half2*)(CH  + base + c)         = h2;
                        else         *(__half2*)(CH2 + base + (c - 128)) = h2;
                    } else {   // EPI == 4
                        if (col < 2048) {
                            const int h = col >> 7, c = col & 127;
                            *(__half2*)(CH + ((size_t)((b * 16 + h) * 2048 + tt)) * 192 + c) = h2;
                        } else if (col < 3072) {
                            *(__half2*)(CH2 + (size_t)r * 1024 + (col - 2048)) = h2;
                        } else if (col < 3584) {
                            *(__half2*)(CH3 + (size_t)r * 512 + (col - 3072)) = h2;
                        } else if (col < 3648) {
                            *(__half2*)(CH4 + (size_t)r * 64 + (col - 3584)) = h2;
                        }
                    }
                }
            }
        }
    }

    // ---- rope tail (ukv kernel only) ----
    if constexpr (EPI == 3) {
        const int nblk = gridDim.x * gridDim.y;
        const int bid = blockIdx.y * gridDim.x + blockIdx.x;
        for (int idx = bid * 256 + tid; idx < NROPE_Q + NROPE_K; idx += nblk * 256) {
            if (idx < NROPE_Q) {
                int i = idx & 31;
                int rest = idx >> 5;
                int bh = rest >> 11, t = rest & 2047;
                int b = bh >> 4, h = bh & 15;
                const __half* base = g_qroth + ((size_t)(b * TSEQ + t)) * 1024 + h * 64;
                float o1, o2;
                rope_pair(__half2float(base[i]), __half2float(base[i + 32]), i, t, o1, o2);
                __half* dst = g_qh + ((size_t)bh * TSEQ + t) * DQK + 128;
                dst[i]      = __float2half_rn(o1);
                dst[i + 32] = __float2half_rn(o2);
            } else {
                int j = idx - NROPE_Q;
                int i = j & 31;
                int rest = j >> 5;
                int t = rest & 2047;
                const __half* base = g_kroth + (size_t)rest * 64;
                float o1, o2;
                rope_pair(__half2float(base[i]), __half2float(base[i + 32]), i, t, o1, o2);
                __half* dst = g_krh + (size_t)rest * 64;
                dst[i]      = __float2half_rn(o1);
                dst[i + 32] = __float2half_rn(o2);
            }
        }
    }
}

// ---------------- flash attention: Q-in-registers, occ 1, 4 q-tiles/CTA ----------------
// grid (4, 32): CTA bx handles q-tiles {15-bx, 11-bx, bx+4, bx} = 34 equal work units.
// BQ=128, BK=32, 8 warps, occ 1, KV ring x4.
#define QPL  49152
#define KPL  12288
#define VPL  8192
#define KVSTG (KPL + VPL)
#define ATT_SMEM (QPL + 4*KVSTG)   // 131072

__global__ __launch_bounds__(256, 1) void attn_mma(
    const __half* __restrict__ qh, const __half* __restrict__ kh,
    const __half* __restrict__ krh, const __half* __restrict__ vh,
    __half* __restrict__ outh)
{
    extern __shared__ __align__(128) char smem[];
    const uint32_t S0 = smem_u32(smem);
    const int tid = threadIdx.x, wid = tid >> 5, lane = tid & 31;
    const int bx = blockIdx.x;
    const int bh = blockIdx.y;
    const int b = bh >> 4, h = bh & 15;

    const size_t qbase = (size_t)bh * TSEQ * DQK;
    const size_t kbase = (size_t)bh * TSEQ * 128;
    const size_t rbase = (size_t)b * TSEQ * 64;

    const int a_r = lane & 15, a_kh = lane >> 4;
    const int b_n = ((lane >> 4) << 3) + (lane & 7), b_kh = (lane >> 3) & 1;
    const int qrow = wid * 16 + a_r;
    const uint32_t qoff_base = S0 + qrow * 384;
    const int v_tl = lane >> 3, v_r = lane & 7;

    const int qts[4] = {15 - bx, 11 - bx, bx + 4, bx};

#pragma unroll 1
    for (int tix = 0; tix < 4; ++tix) {
        const int qt = qts[tix];
        const int q0 = qt * 128;
        const int nk = 4 * (qt + 1);

        if (tix > 0) {   // drain prior tile's in-flight loads; smem reads all done
            asm volatile("cp.async.wait_group 0;" ::: "memory");
            __syncthreads();
        }

        {   // Q (commit group)
            for (int i = tid; i < 128 * 24; i += 256) {
                int row = i / 24, c = i % 24;
                uint32_t sw = (uint32_t)(row * 384 + ((c ^ (row & 7)) << 4));
                cp16(S0 + sw, qh + qbase + (size_t)(q0 + row) * DQK + c * 8);
            }
            asm volatile("cp.async.commit_group;" ::: "memory");
        }
        auto loadKV = [&](int it) {
            if (it < nk) {
                uint32_t d = S0 + QPL + (uint32_t)(it & 3) * KVSTG;
                int k0 = it * 32;
#pragma unroll
                for (int j = 0; j < 3; ++j) {
                    int i = tid + j * 256;
                    int row = i / 24, c = i % 24;
                    uint32_t sw = (uint32_t)(row * 384 + ((c ^ (row & 7)) << 4));
                    const __half* src = (c < 16)
                        ? kh  + kbase + (size_t)(k0 + row) * 128 + c * 8
                        : krh + rbase + (size_t)(k0 + row) * 64 + (c - 16) * 8;
                    cp16(d + sw, src);
                }
#pragma unroll
                for (int j = 0; j < 2; ++j) {
                    int i = tid + j * 256;
                    int row = i >> 4, c = i & 15;
                    uint32_t sw = (uint32_t)(row * 256 + (((c & 8) | ((c & 7) ^ (row & 7))) << 4));
                    cp16(d + KPL + sw, vh + kbase + (size_t)(k0 + row) * 128 + c * 8);
                }
            }
            asm volatile("cp.async.commit_group;" ::: "memory");
        };

        loadKV(0);
        loadKV(1);

        // wait for Q + KV0 (leave KV1 in flight), then hoist Q fragments
        asm volatile("cp.async.wait_group 1;" ::: "memory");
        __syncthreads();

        uint32_t qf[12][4];
#pragma unroll
        for (int kc = 0; kc < 12; ++kc)
            ldm4(qf[kc], qoff_base + ((((kc * 2 + a_kh)) ^ (qrow & 7)) << 4));

        float o[16][4];
#pragma unroll
        for (int j = 0; j < 16; ++j)
#pragma unroll
            for (int q = 0; q < 4; ++q) o[j][q] = 0.f;
        float l0r = 0.f, l1r = 0.f;

        for (int it = 0; it < nk; ++it) {
            if (it > 0) {
                asm volatile("cp.async.wait_group 1;" ::: "memory");
                __syncthreads();
            }
            loadKV(it + 2);   // stage (it+2)&3 == (it-2)&3, consumed 2 iters ago

            const uint32_t Kb = S0 + QPL + (uint32_t)(it & 3) * KVSTG;
            const uint32_t Vb = Kb + KPL;

            // ---- S = Q K^T (128x32, log2 domain) ----
            float s[4][4];
#pragma unroll
            for (int j = 0; j < 4; ++j)
#pragma unroll
                for (int q = 0; q < 4; ++q) s[j][q] = 0.f;

#pragma unroll 4
            for (int kc = 0; kc < 12; ++kc) {
#pragma unroll
                for (int np = 0; np < 2; ++np) {
                    int krow = np * 16 + b_n;
                    uint32_t ka = Kb + krow * 384 + (((kc * 2 + b_kh) ^ (krow & 7)) << 4);
                    uint32_t kf[4];
                    ldm4(kf, ka);
#pragma unroll
                    for (int t2 = 0; t2 < 2; ++t2)
                        mma16816(s[np * 2 + t2], qf[kc], &kf[t2 * 2]);
                }
            }

            // ---- mask (diagonal block only) ----
            const int k0 = it * 32;
            const int r0 = q0 + wid * 16 + (lane >> 2);
            if (it >= nk - 4) {
#pragma unroll
                for (int nt = 0; nt < 4; ++nt) {
                    int kcol = k0 + nt * 8 + (lane & 3) * 2;
                    if (kcol     > r0)     s[nt][0] = NEG_BIG;
                    if (kcol + 1 > r0)     s[nt][1] = NEG_BIG;
                    if (kcol     > r0 + 8) s[nt][2] = NEG_BIG;
                    if (kcol + 1 > r0 + 8) s[nt][3] = NEG_BIG;
                }
            }

            // ---- fixed-reference softmax ----
            uint32_t ph[2][4];
#pragma unroll
            for (int nt = 0; nt < 4; ++nt) {
                float p0 = ex2(s[nt][0] - SOFT_C);
                float p1 = ex2(s[nt][1] - SOFT_C);
                float p2 = ex2(s[nt][2] - SOFT_C);
                float p3 = ex2(s[nt][3] - SOFT_C);
                l0r += p0 + p1;
                l1r += p2 + p3;
                __half2 h01 = __float22half2_rn(make_float2(p0, p1));
                __half2 h23 = __float22half2_rn(make_float2(p2, p3));
                const int kc2 = nt >> 1, w2 = (nt & 1) * 2;
                ph[kc2][w2]     = *(uint32_t*)&h01;
                ph[kc2][w2 + 1] = *(uint32_t*)&h23;
            }

            // ---- O += P V (same iter) ----
#pragma unroll
            for (int kc = 0; kc < 2; ++kc) {
#pragma unroll
                for (int ng = 0; ng < 8; ++ng) {
                    const int trow = kc * 16 + ((v_tl >> 1) << 3) + v_r;
                    const int c = ng * 2 + (v_tl & 1);
                    uint32_t va = Vb + trow * 256 +
                        ((uint32_t)((c & 8) | ((c & 7) ^ (trow & 7))) << 4);
                    uint32_t vf[4];
                    ldm4t(vf, va);
                    mma16816b(o[ng * 2],     ph[kc], vf[0], vf[2]);
                    mma16816b(o[ng * 2 + 1], ph[kc], vf[1], vf[3]);
                }
            }
        }

        // ---- epilogue for this tile ----
        l0r += __shfl_xor_sync(0xffffffffu, l0r, 1);
        l0r += __shfl_xor_sync(0xffffffffu, l0r, 2);
        l1r += __shfl_xor_sync(0xffffffffu, l1r, 1);
        l1r += __shfl_xor_sync(0xffffffffu, l1r, 2);
        const float inv0 = 1.0f / l0r, inv1 = 1.0f / l1r;
        const int row0 = b * TSEQ + q0 + wid * 16 + (lane >> 2);
#pragma unroll
        for (int j = 0; j < 16; ++j) {
            const int col = h * 128 + j * 8 + (lane & 3) * 2;
            __half2 h2a = __float22half2_rn(make_float2(o[j][0] * inv0, o[j][1] * inv0));
            __half2 h2b = __float22half2_rn(make_float2(o[j][2] * inv1, o[j][3] * inv1));
            *(__half2*)(outh + (size_t)row0 * DM + col)       = h2a;
            *(__half2*)(outh + (size_t)(row0 + 8) * DM + col) = h2b;
        }
    }
}

// ---------------- host-side helpers ----------------
template<int BN, int EPI>
static void run_gemm(const __half* a, const __half* b, float* c,
                     __half* ch, __half* ch2, __half* ch3, __half* ch4,
                     int M, int N, int K) {
    constexpr int SMEM = 3 * (128 * 128 + BN * 128);
    cudaFuncSetAttribute(gemm_s<BN, EPI>, cudaFuncAttributeMaxDynamicSharedMemorySize, SMEM);
    gemm_s<BN, EPI><<<dim3(N / BN, M / 128), 256, SMEM>>>(a, b, c, ch, ch2, ch3, ch4, M, N, K);
}

extern "C" void kernel_launch(void* const* d_in, const int* in_sizes, int n_in,
                              void* d_out, int out_size) {
    const float* x      = (const float*)d_in[0];
    const float* w_q    = (const float*)d_in[1];
    const float* w_dkv  = (const float*)d_in[2];
    const float* w_ukv  = (const float*)d_in[3];
    const float* w_o    = (const float*)d_in[4];
    const float* w_qrot = (const float*)d_in[5];
    const float* w_krot = (const float*)d_in[6];
    float* out = (float*)d_out;

    __half *xh,*wcat,*wuh,*woh,*qroth,*kroth,*p_dkv,*p_attn,*pqh,*pkh,*pkrh,*pvh;
    cudaGetSymbolAddress((void**)&xh,    g_x);
    cudaGetSymbolAddress((void**)&wcat,  g_wcat);
    cudaGetSymbolAddress((void**)&wuh,   g_wukv_h);
    cudaGetSymbolAddress((void**)&woh,   g_wo_h);
    cudaGetSymbolAddress((void**)&qroth, g_qroth);
    cudaGetSymbolAddress((void**)&kroth, g_kroth);
    cudaGetSymbolAddress((void**)&p_dkv, g_dkv);
    cudaGetSymbolAddress((void**)&p_attn,g_attn);
    cudaGetSymbolAddress((void**)&pqh,   g_qh);
    cudaGetSymbolAddress((void**)&pkh,   g_kh);
    cudaGetSymbolAddress((void**)&pkrh,  g_krh);
    cudaGetSymbolAddress((void**)&pvh,   g_vh);

    // 0: all fp32->fp16 conversions
    conv_all<<<(N4_ALL + 255) / 256, 256>>>(x, w_q, w_qrot, w_dkv, w_krot, w_ukv, w_o,
                                            xh, wcat, wuh, woh);
    // 1: fused projection GEMM (q-pack | qrot | dkv | krot)
    run_gemm<128, 4>(xh, wcat, nullptr, pqh, qroth, p_dkv, kroth, BT, NCAT, DM);
    // 2: ukv GEMM with K|V split epilogue + rope tail
    run_gemm<128, 3>(p_dkv, wuh, nullptr, pkh, pvh, nullptr, nullptr, BT, 4096, 512);
    // 3: attention   <- profiled
    cudaFuncSetAttribute(attn_mma, cudaFuncAttributeMaxDynamicSharedMemorySize, ATT_SMEM);
    attn_mma<<<dim3(4, 32), 256, ATT_SMEM>>>(pqh, pkh, pkrh, pvh, p_attn);
    // 4: output projection
    run_gemm<128, 0>(p_attn, woh, out, nullptr, nullptr, nullptr, nullptr, BT, DM, DM);
}

// round 16
// speedup vs baseline: 1.0857x; 1.0857x over previous
#include <cuda_runtime.h>
#include <cuda_fp16.h>
#include <math.h>
#include <cstdint>

#define BT    4096
#define TSEQ  2048
#define DM    2048
#define DQK   192
#define DV    128
#define NCAT  3712
#define ATT_SCALE 0.07216878364870323f
#define SCALE_L2  0.10412736773510762f                  // ATT_SCALE * log2(e)
#define SOFT_C    8.0f
#define NEG_BIG  -1e30f

// ---------------- scratch ----------------
__device__ __half g_x    [BT * DM];
__device__ __half g_wcat [NCAT * DM];
__device__ __half g_wukv_h[4096 * 512];
__device__ __half g_wo_h [DM * DM];
__device__ __half g_qroth[BT * 1024];
__device__ __half g_kroth[BT * 64];
__device__ __half g_dkv  [BT * 512];
__device__ __half g_attn [BT * DM];
__device__ __half g_qh [32 * TSEQ * DQK];
__device__ __half g_kh [32 * TSEQ * 128];
__device__ __half g_krh[ 2 * TSEQ * 64];
__device__ __half g_vh [32 * TSEQ * 128];

// ---------------- PTX helpers ----------------
__device__ __forceinline__ void cp16(uint32_t s, const void* g) {
    asm volatile("cp.async.cg.shared.global [%0], [%1], 16;" :: "r"(s), "l"(g) : "memory");
}
__device__ __forceinline__ uint32_t smem_u32(const void* p) {
    uint32_t a;
    asm("{ .reg .u64 t; cvta.to.shared.u64 t, %1; cvt.u32.u64 %0, t; }" : "=r"(a) : "l"(p));
    return a;
}
__device__ __forceinline__ void ldm4(uint32_t* r, uint32_t addr) {
    asm volatile("ldmatrix.sync.aligned.m8n8.x4.shared.b16 {%0,%1,%2,%3}, [%4];"
        : "=r"(r[0]), "=r"(r[1]), "=r"(r[2]), "=r"(r[3]) : "r"(addr));
}
__device__ __forceinline__ void ldm4t(uint32_t* r, uint32_t addr) {
    asm volatile("ldmatrix.sync.aligned.m8n8.x4.trans.shared.b16 {%0,%1,%2,%3}, [%4];"
        : "=r"(r[0]), "=r"(r[1]), "=r"(r[2]), "=r"(r[3]) : "r"(addr));
}
__device__ __forceinline__ void mma16816(float* c, const uint32_t* a, const uint32_t* b) {
    asm volatile(
        "mma.sync.aligned.m16n8k16.row.col.f32.f16.f16.f32 "
        "{%0,%1,%2,%3}, {%4,%5,%6,%7}, {%8,%9}, {%0,%1,%2,%3};"
        : "+f"(c[0]), "+f"(c[1]), "+f"(c[2]), "+f"(c[3])
        : "r"(a[0]), "r"(a[1]), "r"(a[2]), "r"(a[3]), "r"(b[0]), "r"(b[1]));
}
__device__ __forceinline__ void mma16816b(float* c, const uint32_t* a, uint32_t b0, uint32_t b1) {
    asm volatile(
        "mma.sync.aligned.m16n8k16.row.col.f32.f16.f16.f32 "
        "{%0,%1,%2,%3}, {%4,%5,%6,%7}, {%8,%9}, {%0,%1,%2,%3};"
        : "+f"(c[0]), "+f"(c[1]), "+f"(c[2]), "+f"(c[3])
        : "r"(a[0]), "r"(a[1]), "r"(a[2]), "r"(a[3]), "r"(b0), "r"(b1));
}
__device__ __forceinline__ float ex2(float x) {
    float y;
    asm("ex2.approx.f32 %0, %1;" : "=f"(y) : "f"(x));
    return y;
}

// ---------------- fused converts ----------------
#define N4_X    2097152
#define N4_CAT  1867776
#define N4_UKV  524288
#define N4_WO   1048576
#define N4_ALL  (N4_X + N4_CAT + N4_UKV + N4_WO)

__global__ void conv_all(const float* __restrict__ x,
                         const float* __restrict__ wq, const float* __restrict__ wqr,
                         const float* __restrict__ wdkv, const float* __restrict__ wkr,
                         const float* __restrict__ wukv, const float* __restrict__ wo,
                         __half* __restrict__ gx, __half* __restrict__ gwcat,
                         __half* __restrict__ gwukv, __half* __restrict__ gwo) {
    int i = blockIdx.x * blockDim.x + threadIdx.x;
    if (i >= N4_ALL) return;
    const float* src;
    __half* dst;
    int si, di;
    float sc = 1.f;
    if (i < N4_X) {
        src = x; dst = gx; si = di = i;
    } else if (i < N4_X + N4_CAT) {
        di = i - N4_X;
        dst = gwcat;
        const int row = (int)(((size_t)di * 4) >> 11);
        if (row < 2048)      { src = wq;   si = di;              sc = SCALE_L2; }
        else if (row < 3072) { src = wqr;  si = di - 2048 * 512; sc = SCALE_L2; }
        else if (row < 3584) { src = wdkv; si = di - 3072 * 512; }
        else                 { src = wkr;  si = di - 3584 * 512; }
    } else if (i < N4_X + N4_CAT + N4_UKV) {
        src = wukv; dst = gwukv; si = di = i - N4_X - N4_CAT;
    } else {
        src = wo; dst = gwo; si = di = i - N4_X - N4_CAT - N4_UKV;
    }
    float4 v = ((const float4*)src)[si];
    ((__half2*)dst)[di*2]   = __halves2half2(__float2half_rn(v.x * sc), __float2half_rn(v.y * sc));
    ((__half2*)dst)[di*2+1] = __halves2half2(__float2half_rn(v.z * sc), __float2half_rn(v.w * sc));
}

// ---------------- rope helper ----------------
__device__ __forceinline__ void rope_pair(float x1, float x2, int i, int t,
                                          float& o1, float& o2) {
    const float invf = (float)exp2(-(double)i * (13.287712379549449 / 32.0));
    const float angf = (float)t * invf;
    double sd, cd;
    sincos((double)angf, &sd, &cd);
    const float s = (float)sd, c = (float)cd;
    o1 = x1 * c - x2 * s;
    o2 = x2 * c + x1 * s;
}
#define NROPE_Q (32 * TSEQ * 32)
#define NROPE_K (2 * TSEQ * 32)

// ---------------- single-pass fp16 NT GEMM ----------------
template<int BN, int EPI>
__global__ __launch_bounds__(256, 2)
void gemm_s(const __half* __restrict__ A, const __half* __restrict__ B,
            float* __restrict__ C, __half* __restrict__ CH, __half* __restrict__ CH2,
            __half* __restrict__ CH3, __half* __restrict__ CH4,
            int M, int N, int K)
{
    constexpr int ATILE = 128 * 128;
    constexpr int BTILE = BN * 128;
    constexpr int STG   = ATILE + BTILE;
    constexpr int WN = 4;
    constexpr int MT = 4;
    constexpr int NT = 4;

    extern __shared__ __align__(128) char smem[];
    const uint32_t d0 = smem_u32(smem);

    const int tid = threadIdx.x;
    const int wid = tid >> 5, lane = tid & 31;
    const int wn = wid % WN, wm = wid / WN;
    const int m0 = blockIdx.y * 128;
    const int n0 = blockIdx.x * BN;
    const int l7 = lane & 7;

    float acc[MT][NT][4];
#pragma unroll
    for (int i = 0; i < MT; ++i)
#pragma unroll
        for (int j = 0; j < NT; ++j)
#pragma unroll
            for (int q = 0; q < 4; ++q) acc[i][j][q] = 0.f;

    uint32_t arow[MT], brow[NT / 2];
    const int a_r = lane & 15;
    const int a_kh = lane >> 4;
    const int b_n = ((lane >> 4) << 3) + (lane & 7);
    const int b_kh = (lane >> 3) & 1;
#pragma unroll
    for (int mt = 0; mt < MT; ++mt) arow[mt] = (uint32_t)((wm * 64 + mt * 16 + a_r) * 128);
#pragma unroll
    for (int np = 0; np < NT / 2; ++np) brow[np] = (uint32_t)((wn * 32 + np * 16 + b_n) * 128);

    const int T = K >> 6;
    auto load_tile = [&](int t) {
        if (t < T) {
            const uint32_t d = d0 + (uint32_t)(t % 3) * STG;
            const int k0 = t * 64;
#pragma unroll
            for (int j = 0; j < 4; ++j) {
                const int c = tid + j * 256;
                const int row = c >> 3, ch = c & 7;
                const uint32_t sw = (uint32_t)(row * 128 + ((ch ^ (row & 7)) << 4));
                cp16(d + sw, A + (size_t)(m0 + row) * K + k0 + ch * 8);
            }
#pragma unroll
            for (int j = 0; j < BN / 32; ++j) {
                const int c = tid + j * 256;
                const int row = c >> 3, ch = c & 7;
                const uint32_t sw = (uint32_t)(row * 128 + ((ch ^ (row & 7)) << 4));
                cp16(d + ATILE + sw, B + (size_t)(n0 + row) * K + k0 + ch * 8);
            }
        }
        asm volatile("cp.async.commit_group;" ::: "memory");
    };

    load_tile(0);
    load_tile(1);

    for (int t = 0; t < T; ++t) {
        asm volatile("cp.async.wait_group 1;" ::: "memory");
        __syncthreads();
        load_tile(t + 2);

        const uint32_t AS = d0 + (uint32_t)(t % 3) * STG;
        const uint32_t BS = AS + ATILE;

#pragma unroll
        for (int kk = 0; kk < 4; ++kk) {
            const uint32_t aoff = (uint32_t)(((kk * 2 + a_kh) ^ l7) << 4);
            const uint32_t boff = (uint32_t)(((kk * 2 + b_kh) ^ l7) << 4);
            uint32_t af[MT][4], bf[NT / 2][4];
#pragma unroll
            for (int mt = 0; mt < MT; ++mt)
                ldm4(af[mt], AS + arow[mt] + aoff);
#pragma unroll
            for (int np = 0; np < NT / 2; ++np)
                ldm4(bf[np], BS + brow[np] + boff);
#pragma unroll
            for (int mt = 0; mt < MT; ++mt)
#pragma unroll
                for (int nt = 0; nt < NT; ++nt)
                    mma16816(acc[mt][nt], af[mt], &bf[nt >> 1][(nt & 1) * 2]);
        }
    }

    const int cr = lane >> 2;
    const int cc = (lane & 3) * 2;
#pragma unroll
    for (int mt = 0; mt < MT; ++mt) {
        const int r0 = m0 + wm * 64 + mt * 16 + cr;
#pragma unroll
        for (int nt = 0; nt < NT; ++nt) {
            const int col = n0 + wn * 32 + nt * 8 + cc;
            if constexpr (EPI == 0) {
                *(float2*)(C + (size_t)r0 * N + col)       = make_float2(acc[mt][nt][0], acc[mt][nt][1]);
                *(float2*)(C + (size_t)(r0 + 8) * N + col) = make_float2(acc[mt][nt][2], acc[mt][nt][3]);
            } else {
#pragma unroll
                for (int hf = 0; hf < 2; ++hf) {
                    __half2 h2 = __float22half2_rn(
                        make_float2(acc[mt][nt][hf*2], acc[mt][nt][hf*2+1]));
                    const int r = r0 + hf * 8;
                    const int b = r >> 11, tt = r & 2047;
                    if constexpr (EPI == 3) {
                        const int h = col >> 8, c = col & 255;
                        const size_t base = ((size_t)((b * 16 + h) * 2048 + tt)) * 128;
                        if (c < 128) *(__half2*)(CH  + base + c)         = h2;
                        else         *(__half2*)(CH2 + base + (c - 128)) = h2;
                    } else {   // EPI == 4
                        if (col < 2048) {
                            const int h = col >> 7, c = col & 127;
                            *(__half2*)(CH + ((size_t)((b * 16 + h) * 2048 + tt)) * 192 + c) = h2;
                        } else if (col < 3072) {
                            *(__half2*)(CH2 + (size_t)r * 1024 + (col - 2048)) = h2;
                        } else if (col < 3584) {
                            *(__half2*)(CH3 + (size_t)r * 512 + (col - 3072)) = h2;
                        } else if (col < 3648) {
                            *(__half2*)(CH4 + (size_t)r * 64 + (col - 3584)) = h2;
                        }
                    }
                }
            }
        }
    }

    // ---- rope tail (ukv kernel only) ----
    if constexpr (EPI == 3) {
        const int nblk = gridDim.x * gridDim.y;
        const int bid = blockIdx.y * gridDim.x + blockIdx.x;
        for (int idx = bid * 256 + tid; idx < NROPE_Q + NROPE_K; idx += nblk * 256) {
            if (idx < NROPE_Q) {
                int i = idx & 31;
                int rest = idx >> 5;
                int bh = rest >> 11, t = rest & 2047;
                int b = bh >> 4, h = bh & 15;
                const __half* base = g_qroth + ((size_t)(b * TSEQ + t)) * 1024 + h * 64;
                float o1, o2;
                rope_pair(__half2float(base[i]), __half2float(base[i + 32]), i, t, o1, o2);
                __half* dst = g_qh + ((size_t)bh * TSEQ + t) * DQK + 128;
                dst[i]      = __float2half_rn(o1);
                dst[i + 32] = __float2half_rn(o2);
            } else {
                int j = idx - NROPE_Q;
                int i = j & 31;
                int rest = j >> 5;
                int t = rest & 2047;
                const __half* base = g_kroth + (size_t)rest * 64;
                float o1, o2;
                rope_pair(__half2float(base[i]), __half2float(base[i + 32]), i, t, o1, o2);
                __half* dst = g_krh + (size_t)rest * 64;
                dst[i]      = __float2half_rn(o1);
                dst[i + 32] = __float2half_rn(o2);
            }
        }
    }
}

// ---------------- flash attention: 4 warps x 32 q-rows, occ 2, paired tiles ----------------
// grid (8, 32): CTA bx handles q-tiles {15-bx, bx} (17 equal work units).
// BQ=128 (4 warps x two m16 tiles), BK=32, KV ring x3, 128 threads.
#define QPL  49152
#define KPL  12288
#define VPL  8192
#define KVSTG (KPL + VPL)
#define ATT_SMEM (QPL + 3*KVSTG)   // 110592 -> 2 CTAs/SM

__global__ __launch_bounds__(128, 2) void attn_mma(
    const __half* __restrict__ qh, const __half* __restrict__ kh,
    const __half* __restrict__ krh, const __half* __restrict__ vh,
    __half* __restrict__ outh)
{
    extern __shared__ __align__(128) char smem[];
    const uint32_t S0 = smem_u32(smem);
    const int tid = threadIdx.x, wid = tid >> 5, lane = tid & 31;
    const int bh = blockIdx.y;
    const int b = bh >> 4, h = bh & 15;

    const size_t qbase = (size_t)bh * TSEQ * DQK;
    const size_t kbase = (size_t)bh * TSEQ * 128;
    const size_t rbase = (size_t)b * TSEQ * 64;

    const int a_r = lane & 15, a_kh = lane >> 4;
    const int b_n = ((lane >> 4) << 3) + (lane & 7), b_kh = (lane >> 3) & 1;
    const int v_tl = lane >> 3, v_r = lane & 7;
    // two m16 q-tiles per warp: rows wid*32 + mt*16
    uint32_t qoff[2];
#pragma unroll
    for (int mt = 0; mt < 2; ++mt)
        qoff[mt] = S0 + (uint32_t)((wid * 32 + mt * 16 + a_r) * 384);
    const int q_sw0 = (wid * 32 + a_r) & 7;          // swizzle row parity (same for both mt: +16 preserves &7)

#pragma unroll 1
    for (int half = 0; half < 2; ++half) {
        const int qt = half ? (int)blockIdx.x : 15 - (int)blockIdx.x;
        const int q0 = qt * 128;
        const int nk = 4 * (qt + 1);

        if (half) {
            asm volatile("cp.async.wait_group 0;" ::: "memory");
            __syncthreads();
        }

        {   // Q (commit group): 128 rows x 24 chunks, 128 threads
            for (int i = tid; i < 128 * 24; i += 128) {
                int row = i / 24, c = i % 24;
                uint32_t sw = (uint32_t)(row * 384 + ((c ^ (row & 7)) << 4));
                cp16(S0 + sw, qh + qbase + (size_t)(q0 + row) * DQK + c * 8);
            }
            asm volatile("cp.async.commit_group;" ::: "memory");
        }
        auto loadKV = [&](int it) {
            if (it < nk) {
                uint32_t d = S0 + QPL + (uint32_t)(it % 3) * KVSTG;
                int k0 = it * 32;
#pragma unroll
                for (int j = 0; j < 6; ++j) {           // K: 768 chunks
                    int i = tid + j * 128;
                    int row = i / 24, c = i % 24;
                    uint32_t sw = (uint32_t)(row * 384 + ((c ^ (row & 7)) << 4));
                    const __half* src = (c < 16)
                        ? kh  + kbase + (size_t)(k0 + row) * 128 + c * 8
                        : krh + rbase + (size_t)(k0 + row) * 64 + (c - 16) * 8;
                    cp16(d + sw, src);
                }
#pragma unroll
                for (int j = 0; j < 4; ++j) {           // V: 512 chunks
                    int i = tid + j * 128;
                    int row = i >> 4, c = i & 15;
                    uint32_t sw = (uint32_t)(row * 256 + (((c & 8) | ((c & 7) ^ (row & 7))) << 4));
                    cp16(d + KPL + sw, vh + kbase + (size_t)(k0 + row) * 128 + c * 8);
                }
            }
            asm volatile("cp.async.commit_group;" ::: "memory");
        };

        loadKV(0);
        loadKV(1);

        float o[2][16][4];
#pragma unroll
        for (int mt = 0; mt < 2; ++mt)
#pragma unroll
            for (int j = 0; j < 16; ++j)
#pragma unroll
                for (int q = 0; q < 4; ++q) o[mt][j][q] = 0.f;
        float l0[2] = {0.f, 0.f}, l1[2] = {0.f, 0.f};

        for (int it = 0; it < nk; ++it) {
            asm volatile("cp.async.wait_group 1;" ::: "memory");
            __syncthreads();
            loadKV(it + 2);

            const uint32_t Kb = S0 + QPL + (uint32_t)(it % 3) * KVSTG;
            const uint32_t Vb = Kb + KPL;

            // ---- S = Q K^T: two m-tiles share each K fragment ----
            float s[2][4][4];
#pragma unroll
            for (int mt = 0; mt < 2; ++mt)
#pragma unroll
                for (int j = 0; j < 4; ++j)
#pragma unroll
                    for (int q = 0; q < 4; ++q) s[mt][j][q] = 0.f;

#pragma unroll 4
            for (int kc = 0; kc < 12; ++kc) {
                const uint32_t qa_off = (uint32_t)((((kc * 2 + a_kh)) ^ q_sw0) << 4);
                uint32_t qf[2][4];
                ldm4(qf[0], qoff[0] + qa_off);
                ldm4(qf[1], qoff[1] + qa_off);
#pragma unroll
                for (int np = 0; np < 2; ++np) {
                    int krow = np * 16 + b_n;
                    uint32_t ka = Kb + krow * 384 + (((kc * 2 + b_kh) ^ (krow & 7)) << 4);
                    uint32_t kf[4];
                    ldm4(kf, ka);
#pragma unroll
                    for (int mt = 0; mt < 2; ++mt)
#pragma unroll
                        for (int t2 = 0; t2 < 2; ++t2)
                            mma16816(s[mt][np * 2 + t2], qf[mt], &kf[t2 * 2]);
                }
            }

            // ---- mask (diagonal block only) ----
            const int k0 = it * 32;
            if (it >= nk - 4) {
#pragma unroll
                for (int mt = 0; mt < 2; ++mt) {
                    const int r0 = q0 + wid * 32 + mt * 16 + (lane >> 2);
#pragma unroll
                    for (int nt = 0; nt < 4; ++nt) {
                        int kcol = k0 + nt * 8 + (lane & 3) * 2;
                        if (kcol     > r0)     s[mt][nt][0] = NEG_BIG;
                        if (kcol + 1 > r0)     s[mt][nt][1] = NEG_BIG;
                        if (kcol     > r0 + 8) s[mt][nt][2] = NEG_BIG;
                        if (kcol + 1 > r0 + 8) s[mt][nt][3] = NEG_BIG;
                    }
                }
            }

            // ---- fixed-reference softmax ----
            uint32_t ph[2][2][4];
#pragma unroll
            for (int mt = 0; mt < 2; ++mt)
#pragma unroll
                for (int nt = 0; nt < 4; ++nt) {
                    float p0 = ex2(s[mt][nt][0] - SOFT_C);
                    float p1 = ex2(s[mt][nt][1] - SOFT_C);
                    float p2 = ex2(s[mt][nt][2] - SOFT_C);
                    float p3 = ex2(s[mt][nt][3] - SOFT_C);
                    l0[mt] += p0 + p1;
                    l1[mt] += p2 + p3;
                    __half2 h01 = __float22half2_rn(make_float2(p0, p1));
                    __half2 h23 = __float22half2_rn(make_float2(p2, p3));
                    const int kc2 = nt >> 1, w2 = (nt & 1) * 2;
                    ph[mt][kc2][w2]     = *(uint32_t*)&h01;
                    ph[mt][kc2][w2 + 1] = *(uint32_t*)&h23;
                }

            // ---- O += P V: both m-tiles share each V fragment ----
#pragma unroll
            for (int kc = 0; kc < 2; ++kc) {
#pragma unroll
                for (int ng = 0; ng < 8; ++ng) {
                    const int trow = kc * 16 + ((v_tl >> 1) << 3) + v_r;
                    const int c = ng * 2 + (v_tl & 1);
                    uint32_t va = Vb + trow * 256 +
                        ((uint32_t)((c & 8) | ((c & 7) ^ (trow & 7))) << 4);
                    uint32_t vf[4];
                    ldm4t(vf, va);
#pragma unroll
                    for (int mt = 0; mt < 2; ++mt) {
                        mma16816b(o[mt][ng * 2],     ph[mt][kc], vf[0], vf[2]);
                        mma16816b(o[mt][ng * 2 + 1], ph[mt][kc], vf[1], vf[3]);
                    }
                }
            }
        }

        // ---- epilogue ----
#pragma unroll
        for (int mt = 0; mt < 2; ++mt) {
            float a0 = l0[mt], a1 = l1[mt];
            a0 += __shfl_xor_sync(0xffffffffu, a0, 1);
            a0 += __shfl_xor_sync(0xffffffffu, a0, 2);
            a1 += __shfl_xor_sync(0xffffffffu, a1, 1);
            a1 += __shfl_xor_sync(0xffffffffu, a1, 2);
            const float inv0 = 1.0f / a0, inv1 = 1.0f / a1;
            const int row0 = b * TSEQ + q0 + wid * 32 + mt * 16 + (lane >> 2);
#pragma unroll
            for (int j = 0; j < 16; ++j) {
                const int col = h * 128 + j * 8 + (lane & 3) * 2;
                __half2 h2a = __float22half2_rn(make_float2(o[mt][j][0] * inv0, o[mt][j][1] * inv0));
                __half2 h2b = __float22half2_rn(make_float2(o[mt][j][2] * inv1, o[mt][j][3] * inv1));
                *(__half2*)(outh + (size_t)row0 * DM + col)       = h2a;
                *(__half2*)(outh + (size_t)(row0 + 8) * DM + col) = h2b;
            }
        }
    }
}

// ---------------- host-side helpers ----------------
template<int BN, int EPI>
static void run_gemm(const __half* a, const __half* b, float* c,
                     __half* ch, __half* ch2, __half* ch3, __half* ch4,
                     int M, int N, int K) {
    constexpr int SMEM = 3 * (128 * 128 + BN * 128);
    cudaFuncSetAttribute(gemm_s<BN, EPI>, cudaFuncAttributeMaxDynamicSharedMemorySize, SMEM);
    gemm_s<BN, EPI><<<dim3(N / BN, M / 128), 256, SMEM>>>(a, b, c, ch, ch2, ch3, ch4, M, N, K);
}

extern "C" void kernel_launch(void* const* d_in, const int* in_sizes, int n_in,
                              void* d_out, int out_size) {
    const float* x      = (const float*)d_in[0];
    const float* w_q    = (const float*)d_in[1];
    const float* w_dkv  = (const float*)d_in[2];
    const float* w_ukv  = (const float*)d_in[3];
    const float* w_o    = (const float*)d_in[4];
    const float* w_qrot = (const float*)d_in[5];
    const float* w_krot = (const float*)d_in[6];
    float* out = (float*)d_out;

    __half *xh,*wcat,*wuh,*woh,*qroth,*kroth,*p_dkv,*p_attn,*pqh,*pkh,*pkrh,*pvh;
    cudaGetSymbolAddress((void**)&xh,    g_x);
    cudaGetSymbolAddress((void**)&wcat,  g_wcat);
    cudaGetSymbolAddress((void**)&wuh,   g_wukv_h);
    cudaGetSymbolAddress((void**)&woh,   g_wo_h);
    cudaGetSymbolAddress((void**)&qroth, g_qroth);
    cudaGetSymbolAddress((void**)&kroth, g_kroth);
    cudaGetSymbolAddress((void**)&p_dkv, g_dkv);
    cudaGetSymbolAddress((void**)&p_attn,g_attn);
    cudaGetSymbolAddress((void**)&pqh,   g_qh);
    cudaGetSymbolAddress((void**)&pkh,   g_kh);
    cudaGetSymbolAddress((void**)&pkrh,  g_krh);
    cudaGetSymbolAddress((void**)&pvh,   g_vh);

    // 0: all fp32->fp16 conversions
    conv_all<<<(N4_ALL + 255) / 256, 256>>>(x, w_q, w_qrot, w_dkv, w_krot, w_ukv, w_o,
                                            xh, wcat, wuh, woh);
    // 1: fused projection GEMM (q-pack | qrot | dkv | krot)
    run_gemm<128, 4>(xh, wcat, nullptr, pqh, qroth, p_dkv, kroth, BT, NCAT, DM);
    // 2: ukv GEMM with K|V split epilogue + rope tail
    run_gemm<128, 3>(p_dkv, wuh, nullptr, pkh, pvh, nullptr, nullptr, BT, 4096, 512);
    // 3: attention   <- profiled
    cudaFuncSetAttribute(attn_mma, cudaFuncAttributeMaxDynamicSharedMemorySize, ATT_SMEM);
    attn_mma<<<dim3(8, 32), 128, ATT_SMEM>>>(pqh, pkh, pkrh, pvh, p_attn);
    // 4: output projection
    run_gemm<128, 0>(p_attn, woh, out, nullptr, nullptr, nullptr, nullptr, BT, DM, DM);
}